// round 8
// baseline (speedup 1.0000x reference)
#include <cuda_runtime.h>

// PointNetSaModule: gather(K=16) -> mask -> [67->64->64->128] MLP (BN folded) -> max over K.
// FFMA2 row-pair packing, thread tile = 8 row-pairs x 4 channels.
// R7: 256 threads / 8 warps -> ~255 reg budget so ptxas prefetches LDS across cins.

typedef unsigned long long ULL;

#define HW_SZ  65536
#define NS_SZ  16384
#define OUT_ONE (4 * 16384 * 128)

#define THREADS 256
#define WARPS   8

#define OFF_W0   0                  // 67*64 (rows permuted: feats 0..63, xyz-diff 64..66)
#define OFF_W1   4288
#define OFF_W2   (4288 + 4096)
#define OFF_T0   (OFF_W2 + 8192)
#define OFF_T1   (OFF_T0 + 64)
#define OFF_T2   (OFF_T1 + 64)
#define OFF_S0   (OFF_T2 + 128)
#define OFF_S1   (OFF_S0 + 64)
#define OFF_S2   (OFF_S1 + 64)
#define OFF_ACT  (OFF_S2 + 128)     // 16B aligned
#define ACT_ULL_PER_WARP 1088       // 68 cins x 16 pairs
#define SMEM_FLOATS (OFF_ACT + WARPS * 2 * ACT_ULL_PER_WARP)
#define SMEM_BYTES  (SMEM_FLOATS * 4)   // ~138 KB

__device__ __forceinline__ ULL pack2_dup(float v) {
    ULL r; asm("mov.b64 %0, {%1, %1};" : "=l"(r) : "f"(v)); return r;
}
__device__ __forceinline__ ULL pack2(float a, float b) {
    ULL r; asm("mov.b64 %0, {%1, %2};" : "=l"(r) : "f"(a), "f"(b)); return r;
}
__device__ __forceinline__ float2 unpack2(ULL v) {
    float2 f; asm("mov.b64 {%0, %1}, %2;" : "=f"(f.x), "=f"(f.y) : "l"(v)); return f;
}
__device__ __forceinline__ void ffma2(ULL& acc, ULL x, ULL w) {
    asm("fma.rn.f32x2 %0, %1, %2, %0;" : "+l"(acc) : "l"(x), "l"(w));
}

// act layout: ULL index = c*16 + (pair ^ sw(c)),  sw(c) = ((c>>1)&7)*2  (even -> pairs stay
// ulonglong2-adjacent). physical = [(8hi)^(sw&8)] + [(2r)^(sw&6)] (disjoint bits).

#define RUN_CIN(u, WS) do {                                                     \
    const int sw  = (((u) >> 1) & 7) * 2;                                       \
    const ULL* xr = ((sw & 8) ? pB : pA) + (u) * 16;                            \
    ulonglong2 x0 = *(const ulonglong2*)(xr + (0 ^ (sw & 6)));                  \
    ulonglong2 x1 = *(const ulonglong2*)(xr + (2 ^ (sw & 6)));                  \
    ulonglong2 x2 = *(const ulonglong2*)(xr + (4 ^ (sw & 6)));                  \
    ulonglong2 x3 = *(const ulonglong2*)(xr + (6 ^ (sw & 6)));                  \
    float4 wv = *(const float4*)(wl + (u) * (WS));                              \
    ULL w0 = pack2_dup(wv.x), w1 = pack2_dup(wv.y);                             \
    ULL w2 = pack2_dup(wv.z), w3 = pack2_dup(wv.w);                             \
    ffma2(acc[ 0], x0.x, w0); ffma2(acc[ 1], x0.x, w1);                         \
    ffma2(acc[ 2], x0.x, w2); ffma2(acc[ 3], x0.x, w3);                         \
    ffma2(acc[ 4], x0.y, w0); ffma2(acc[ 5], x0.y, w1);                         \
    ffma2(acc[ 6], x0.y, w2); ffma2(acc[ 7], x0.y, w3);                         \
    ffma2(acc[ 8], x1.x, w0); ffma2(acc[ 9], x1.x, w1);                         \
    ffma2(acc[10], x1.x, w2); ffma2(acc[11], x1.x, w3);                         \
    ffma2(acc[12], x1.y, w0); ffma2(acc[13], x1.y, w1);                         \
    ffma2(acc[14], x1.y, w2); ffma2(acc[15], x1.y, w3);                         \
    ffma2(acc[16], x2.x, w0); ffma2(acc[17], x2.x, w1);                         \
    ffma2(acc[18], x2.x, w2); ffma2(acc[19], x2.x, w3);                         \
    ffma2(acc[20], x2.y, w0); ffma2(acc[21], x2.y, w1);                         \
    ffma2(acc[22], x2.y, w2); ffma2(acc[23], x2.y, w3);                         \
    ffma2(acc[24], x3.x, w0); ffma2(acc[25], x3.x, w1);                         \
    ffma2(acc[26], x3.x, w2); ffma2(acc[27], x3.x, w3);                         \
    ffma2(acc[28], x3.y, w0); ffma2(acc[29], x3.y, w1);                         \
    ffma2(acc[30], x3.y, w2); ffma2(acc[31], x3.y, w3);                         \
} while (0)

template<int NB, int NR, int WS>
__device__ __forceinline__ void run_layer(ULL acc[32], const ULL* pA, const ULL* pB,
                                          const float* wl)
{
    #pragma unroll
    for (int j = 0; j < 32; j++) acc[j] = 0ull;
    #pragma unroll 1
    for (int t = 0; t < NB; t++) {
        #pragma unroll
        for (int u = 0; u < 16; u++) RUN_CIN(u, WS);
        pA += 256; pB += 256; wl += 16 * WS;
    }
    #pragma unroll
    for (int u = 0; u < NR; u++) RUN_CIN(u, WS);
}

__global__ void __launch_bounds__(THREADS, 1)
pointnet_sa_kernel(
    const float* __restrict__ xyz, const float* __restrict__ pts,
    const float* __restrict__ xyzs, const int* __restrict__ nbr,
    const float* __restrict__ vmask,
    const float* __restrict__ w0, const float* __restrict__ b0,
    const float* __restrict__ g0, const float* __restrict__ be0,
    const float* __restrict__ m0, const float* __restrict__ v0,
    const float* __restrict__ w1, const float* __restrict__ b1,
    const float* __restrict__ g1, const float* __restrict__ be1,
    const float* __restrict__ m1, const float* __restrict__ v1,
    const float* __restrict__ w2, const float* __restrict__ b2,
    const float* __restrict__ g2, const float* __restrict__ be2,
    const float* __restrict__ m2, const float* __restrict__ v2,
    float* __restrict__ out, int copies)
{
    extern __shared__ float sm[];
    const int tid = threadIdx.x;

    // ---- BN fold ----
    if (tid < 64) {
        float s = g0[tid] * rsqrtf(v0[tid] + 1e-5f);
        sm[OFF_S0 + tid] = s;
        sm[OFF_T0 + tid] = (b0[tid] - m0[tid]) * s + be0[tid];
        float s1 = g1[tid] * rsqrtf(v1[tid] + 1e-5f);
        sm[OFF_S1 + tid] = s1;
        sm[OFF_T1 + tid] = (b1[tid] - m1[tid]) * s1 + be1[tid];
    }
    if (tid < 128) {
        float s = g2[tid] * rsqrtf(v2[tid] + 1e-5f);
        sm[OFF_S2 + tid] = s;
        sm[OFF_T2 + tid] = (b2[tid] - m2[tid]) * s + be2[tid];
    }
    __syncthreads();
    for (int i = tid; i < 4288; i += THREADS) {
        int r = i >> 6, c = i & 63;
        int sr = (r < 64) ? (r + 3) : (r - 64);   // feats first, xyz-diff rows last
        sm[OFF_W0 + i] = w0[sr * 64 + c] * sm[OFF_S0 + c];
    }
    for (int i = tid; i < 4096; i += THREADS) sm[OFF_W1 + i] = w1[i] * sm[OFF_S1 + (i & 63)];
    for (int i = tid; i < 8192; i += THREADS) sm[OFF_W2 + i] = w2[i] * sm[OFF_S2 + (i & 127)];
    __syncthreads();

    const int lane = tid & 31;
    const int warp = tid >> 5;
    const int lh   = lane & 15;   // channel lane: ch = 4*lh .. 4*lh+3
    const int hi   = lane >> 4;   // pair half / K-group selector
    ULL* actw = (ULL*)(sm + OFF_ACT) + warp * ACT_ULL_PER_WARP;
    float* actwf = (float*)actw;

    // ---- gather: lane owns row=lane (rows 0-15 -> group hi=0, 16-31 -> hi=1) ----
    {
        const int grp = blockIdx.x * (2 * WARPS) + warp * 2 + (lane >> 4);
        const int b = grp >> 14;
        const int n = grp & (NS_SZ - 1);
        const int e = grp * 16 + (lane & 15);
        const int idx = nbr[e];
        const float mk = vmask[e];
        const int p  = lane >> 1;
        const int hf = lane & 1;
        const float4* pp = (const float4*)(pts + (b * HW_SZ + idx) * 64);
        #pragma unroll
        for (int i = 0; i < 16; i++) {
            float4 v = pp[i];
            v.x *= mk; v.y *= mk; v.z *= mk; v.w *= mk;
            #pragma unroll
            for (int j = 0; j < 4; j++) {
                int c = 4 * i + j;
                int sw = ((c >> 1) & 7) * 2;
                actwf[(c * 16 + (p ^ sw)) * 2 + hf] = (&v.x)[j];
            }
        }
        const float* cp = xyzs + (b * NS_SZ + n) * 3;
        const float* gx = xyz + (b * HW_SZ + idx) * 3;
        #pragma unroll
        for (int j = 0; j < 3; j++) {
            int c = 64 + j;
            int sw = ((c >> 1) & 7) * 2;
            actwf[(c * 16 + (p ^ sw)) * 2 + hf] = gx[j] * mk - cp[j];
        }
    }
    __syncwarp();

    const ULL* pA = actw + 8 * hi;
    const ULL* pB = actw + 8 - 8 * hi;

    // epilogue swizzles for this thread's output cins c' = 4lh..4lh+3
    const int sw01 = ((lh * 2) & 7) * 2;
    const int sw23 = ((lh * 2 + 1) & 7) * 2;
    ULL* row0 = actw + (4 * lh + 0) * 16;
    ULL* row1 = actw + (4 * lh + 1) * 16;
    ULL* row2 = actw + (4 * lh + 2) * 16;
    ULL* row3 = actw + (4 * lh + 3) * 16;

    // ---- layers 0 and 1 ----
    #pragma unroll 1
    for (int L = 0; L < 2; L++) {
        ULL acc[32];
        if (L == 0) run_layer<4, 3, 64>(acc, pA, pB, sm + OFF_W0 + 4 * lh);
        else        run_layer<4, 0, 64>(acc, pA, pB, sm + OFF_W1 + 4 * lh);
        float4 bt = *(const float4*)(sm + (L == 0 ? OFF_T0 : OFF_T1) + 4 * lh);
        __syncwarp();
        #pragma unroll
        for (int q = 0; q < 8; q++) {
            const int p = 8 * hi + q;
            const int i01 = p ^ sw01, i23 = p ^ sw23;
            float2 a;
            a = unpack2(acc[4*q+0]); row0[i01] = pack2(fmaxf(a.x+bt.x,0.f), fmaxf(a.y+bt.x,0.f));
            a = unpack2(acc[4*q+1]); row1[i01] = pack2(fmaxf(a.x+bt.y,0.f), fmaxf(a.y+bt.y,0.f));
            a = unpack2(acc[4*q+2]); row2[i23] = pack2(fmaxf(a.x+bt.z,0.f), fmaxf(a.y+bt.z,0.f));
            a = unpack2(acc[4*q+3]); row3[i23] = pack2(fmaxf(a.x+bt.w,0.f), fmaxf(a.y+bt.w,0.f));
        }
        __syncwarp();
    }

    // ---- layer 2 (two 64-ch passes) + thread-local max over K + store ----
    const int grp = blockIdx.x * (2 * WARPS) + warp * 2 + hi;
    #pragma unroll 1
    for (int pass = 0; pass < 2; pass++) {
        ULL acc[32];
        run_layer<4, 0, 128>(acc, pA, pB, sm + OFF_W2 + 64 * pass + 4 * lh);
        float4 bt = *(const float4*)(sm + OFF_T2 + 64 * pass + 4 * lh);
        float4 o;
        #pragma unroll
        for (int j = 0; j < 4; j++) {
            float m = -1e30f;
            #pragma unroll
            for (int q = 0; q < 8; q++) {
                float2 a = unpack2(acc[4*q + j]);
                m = fmaxf(m, fmaxf(a.x, a.y));
            }
            (&o.x)[j] = fmaxf(m + (&bt.x)[j], 0.f);
        }
        const long off = (long)grp * 128 + 64 * pass + 4 * lh;
        *(float4*)(out + off) = o;
        if (copies > 1) *(float4*)(out + OUT_ONE + off) = o;
    }
}

extern "C" void kernel_launch(void* const* d_in, const int* in_sizes, int n_in,
                              void* d_out, int out_size)
{
    const float* xyz   = (const float*)d_in[0];
    const float* pts   = (const float*)d_in[1];
    const float* xyzs  = (const float*)d_in[2];
    const int*   nbr   = (const int*)  d_in[3];
    const float* vmask = (const float*)d_in[4];
    const float* w0  = (const float*)d_in[5];
    const float* b0  = (const float*)d_in[6];
    const float* g0  = (const float*)d_in[7];
    const float* be0 = (const float*)d_in[8];
    const float* m0  = (const float*)d_in[9];
    const float* v0  = (const float*)d_in[10];
    const float* w1  = (const float*)d_in[11];
    const float* b1  = (const float*)d_in[12];
    const float* g1  = (const float*)d_in[13];
    const float* be1 = (const float*)d_in[14];
    const float* m1  = (const float*)d_in[15];
    const float* v1  = (const float*)d_in[16];
    const float* w2  = (const float*)d_in[17];
    const float* b2  = (const float*)d_in[18];
    const float* g2  = (const float*)d_in[19];
    const float* be2 = (const float*)d_in[20];
    const float* m2  = (const float*)d_in[21];
    const float* v2  = (const float*)d_in[22];

    int copies = (out_size >= 2 * OUT_ONE) ? 2 : 1;

    cudaFuncSetAttribute(pointnet_sa_kernel,
                         cudaFuncAttributeMaxDynamicSharedMemorySize, SMEM_BYTES);

    const int blocks = (4 * NS_SZ) / (2 * WARPS);   // 4096
    pointnet_sa_kernel<<<blocks, THREADS, SMEM_BYTES>>>(
        xyz, pts, xyzs, nbr, vmask,
        w0, b0, g0, be0, m0, v0,
        w1, b1, g1, be1, m1, v1,
        w2, b2, g2, be2, m2, v2,
        (float*)d_out, copies);
}